// round 2
// baseline (speedup 1.0000x reference)
#include <cuda_runtime.h>
#include <cstdint>
#include <cstddef>

// Problem constants (fixed by the dataset)
#define NN 100000
#define NE 640000
#define DD 128
#define BN_EPS 1e-5f

#define BM   64     // rows per GEMM tile
#define PAD  68     // padded row stride of transposed A tile (conflict-free + f4-aligned)
#define KTOT 256    // fused K: 128 (mean_agg @ W_l^T) + 128 (relu(x) @ W_r^T)

// Device scratch (allocation-free rule: __device__ globals)
__device__ __align__(16) float g_agg[(size_t)NN * DD];   // scatter-add accumulator
__device__ __align__(16) float g_cnt[NN];                // in-degree counts
__device__ __align__(16) float g_stats[4 * DD];          // [colsum | colsumsq | scale | shift]

// ---------------------------------------------------------------------------
// Zero the scratch buffers (pure-kernel replacement for cudaMemsetAsync).
// 12,800,000 agg floats + 100,000 cnt + 256 stats = 12,900,256 floats.
// float4 over agg (3.2M f4), scalar tail for cnt/stats.
// ---------------------------------------------------------------------------
__global__ void init_kernel()
{
    const int n4 = NN * DD / 4;                 // 3,200,000 float4s
    int stride = gridDim.x * blockDim.x;
    float4 z4 = make_float4(0.f, 0.f, 0.f, 0.f);
    float4* a4 = (float4*)g_agg;
    for (int i = blockIdx.x * blockDim.x + threadIdx.x; i < n4; i += stride)
        a4[i] = z4;
    for (int i = blockIdx.x * blockDim.x + threadIdx.x; i < NN; i += stride)
        g_cnt[i] = 0.f;
    if (blockIdx.x == 0 && threadIdx.x < 2 * DD)
        g_stats[threadIdx.x] = 0.f;
}

// ---------------------------------------------------------------------------
// Scatter: one warp per edge. lane l handles cols 4l..4l+3.
// agg[dst] += relu(x[src]); cnt[dst] += 1
// ---------------------------------------------------------------------------
__global__ void scatter_kernel(const float* __restrict__ x, const int* __restrict__ ei)
{
    int t = blockIdx.x * blockDim.x + threadIdx.x;
    int e = t >> 5;
    if (e >= NE) return;
    int lane = t & 31;
    int src = __ldg(ei + e);
    int dst = __ldg(ei + NE + e);

    float4 v = __ldg((const float4*)(x + (size_t)src * DD) + lane);
    v.x = fmaxf(v.x, 0.f); v.y = fmaxf(v.y, 0.f);
    v.z = fmaxf(v.z, 0.f); v.w = fmaxf(v.w, 0.f);

    float* p = g_agg + (size_t)dst * DD + lane * 4;
    asm volatile("red.global.add.v4.f32 [%0], {%1, %2, %3, %4};"
                 :: "l"(p), "f"(v.x), "f"(v.y), "f"(v.z), "f"(v.w) : "memory");
    if (lane == 0) atomicAdd(&g_cnt[dst], 1.0f);
}

// ---------------------------------------------------------------------------
// Fused GEMM + BN-stat accumulation.
// out[i][j] = sum_k A[i][k] * Wc[j][k] + b_l[j],
//   A[i][k] = agg[i][k]/max(cnt,1)   (k <  128)
//           = relu(x[i][k-128])      (k >= 128)
//   Wc[j][k] = W_l[j][k] (k<128), W_r[j][k-128] (k>=128)
// Block: 256 threads = 16(tx: cols) x 16(ty: rows); thread tile 4 rows x 8 cols,
// cols split as {4*tx..4*tx+3} and {64+4*tx..64+4*tx+3} -> conflict-free W LDS.128.
// Persistent grid of 148 blocks; W (128KB) loaded once per block into smem.
// ---------------------------------------------------------------------------
__global__ void __launch_bounds__(256, 1) fused_gemm(
    const float* __restrict__ x, const float* __restrict__ Wl,
    const float* __restrict__ bl, const float* __restrict__ Wr,
    float* __restrict__ out)
{
    extern __shared__ float sm[];
    float* Ws   = sm;                    // [KTOT][DD]   = 32768 floats (128KB)
    float* As   = sm + KTOT * DD;        // [KTOT][PAD]  = 17408 floats (68KB)
    float* invs = As + KTOT * PAD;       // [BM]

    const int tid = threadIdx.x;
    const int tx  = tid & 15;
    const int ty  = tid >> 4;

    // --- Load combined weights into smem, k-major: Ws[k][j] ---
    #pragma unroll
    for (int it = 0; it < 16; ++it) {
        int q  = it * 256 + tid;     // 0..4095
        int j  = q & 127;            // output col
        int kq = q >> 7;             // float4 index along k (0..31)
        float4 vl = __ldg((const float4*)Wl + j * 32 + kq);
        float4 vr = __ldg((const float4*)Wr + j * 32 + kq);
        int k0 = kq * 4;
        Ws[(k0 + 0) * DD + j] = vl.x;
        Ws[(k0 + 1) * DD + j] = vl.y;
        Ws[(k0 + 2) * DD + j] = vl.z;
        Ws[(k0 + 3) * DD + j] = vl.w;
        Ws[(128 + k0 + 0) * DD + j] = vr.x;
        Ws[(128 + k0 + 1) * DD + j] = vr.y;
        Ws[(128 + k0 + 2) * DD + j] = vr.z;
        Ws[(128 + k0 + 3) * DD + j] = vr.w;
    }

    float bias[8];
    #pragma unroll
    for (int c = 0; c < 4; ++c) {
        bias[c]     = __ldg(bl + tx * 4 + c);
        bias[c + 4] = __ldg(bl + 64 + tx * 4 + c);
    }

    float cs[8], cq[8];
    #pragma unroll
    for (int c = 0; c < 8; ++c) { cs[c] = 0.f; cq[c] = 0.f; }

    const int ntiles = (NN + BM - 1) / BM;
    for (int tile = blockIdx.x; tile < ntiles; tile += gridDim.x) {
        const int rowbase = tile * BM;

        __syncthreads();   // previous tile's compute finished (As reuse)
        if (tid < BM) {
            int row = rowbase + tid;
            invs[tid] = (row < NN) ? 1.0f / fmaxf(g_cnt[row], 1.0f) : 0.0f;
        }
        __syncthreads();   // invs visible (also covers initial Ws fill)

        // Load A tile transposed: As[k][r]. r varies within warp -> conflict-free STS.
        #pragma unroll
        for (int it = 0; it < 16; ++it) {
            int q   = it * 256 + tid;   // 0..4095
            int r   = q & 63;
            int kq  = q >> 6;           // 0..63 (float4 index over 256-wide K)
            int row = rowbase + r;
            float4 v = make_float4(0.f, 0.f, 0.f, 0.f);
            if (kq < 32) {              // warp-uniform branch
                if (row < NN) {
                    v = *((const float4*)(g_agg + (size_t)row * DD) + kq);
                    float s = invs[r];
                    v.x *= s; v.y *= s; v.z *= s; v.w *= s;
                }
            } else {
                if (row < NN) {
                    v = __ldg((const float4*)(x + (size_t)row * DD) + (kq - 32));
                    v.x = fmaxf(v.x, 0.f); v.y = fmaxf(v.y, 0.f);
                    v.z = fmaxf(v.z, 0.f); v.w = fmaxf(v.w, 0.f);
                }
            }
            int k0 = kq * 4;
            As[(k0 + 0) * PAD + r] = v.x;
            As[(k0 + 1) * PAD + r] = v.y;
            As[(k0 + 2) * PAD + r] = v.z;
            As[(k0 + 3) * PAD + r] = v.w;
        }
        __syncthreads();

        float acc[4][8];
        #pragma unroll
        for (int r = 0; r < 4; ++r)
            #pragma unroll
            for (int c = 0; c < 8; ++c)
                acc[r][c] = bias[c];

        #pragma unroll 16
        for (int k = 0; k < KTOT; ++k) {
            float4 a  = *(const float4*)&As[k * PAD + ty * 4];
            float4 w0 = *(const float4*)&Ws[k * DD + tx * 4];
            float4 w1 = *(const float4*)&Ws[k * DD + 64 + tx * 4];
            float av[4] = {a.x, a.y, a.z, a.w};
            float wv[8] = {w0.x, w0.y, w0.z, w0.w, w1.x, w1.y, w1.z, w1.w};
            #pragma unroll
            for (int r = 0; r < 4; ++r)
                #pragma unroll
                for (int c = 0; c < 8; ++c)
                    acc[r][c] = fmaf(av[r], wv[c], acc[r][c]);
        }

        // Store + accumulate BN column stats in registers
        #pragma unroll
        for (int r = 0; r < 4; ++r) {
            int row = rowbase + ty * 4 + r;
            if (row < NN) {
                float4 o0 = make_float4(acc[r][0], acc[r][1], acc[r][2], acc[r][3]);
                float4 o1 = make_float4(acc[r][4], acc[r][5], acc[r][6], acc[r][7]);
                *((float4*)(out + (size_t)row * DD) + tx)      = o0;
                *((float4*)(out + (size_t)row * DD + 64) + tx) = o1;
                #pragma unroll
                for (int c = 0; c < 8; ++c) {
                    cs[c] += acc[r][c];
                    cq[c] += acc[r][c] * acc[r][c];
                }
            }
        }
    }

    // --- Block reduction of column stats, then 2 atomics per column per block ---
    __syncthreads();
    float* red = As;   // reuse (needs 16*128 floats)
    #pragma unroll
    for (int c = 0; c < 4; ++c) {
        red[ty * DD + tx * 4 + c]      = cs[c];
        red[ty * DD + 64 + tx * 4 + c] = cs[c + 4];
    }
    __syncthreads();
    if (tid < DD) {
        float s = 0.f;
        #pragma unroll
        for (int t = 0; t < 16; ++t) s += red[t * DD + tid];
        atomicAdd(&g_stats[tid], s);
    }
    __syncthreads();
    #pragma unroll
    for (int c = 0; c < 4; ++c) {
        red[ty * DD + tx * 4 + c]      = cq[c];
        red[ty * DD + 64 + tx * 4 + c] = cq[c + 4];
    }
    __syncthreads();
    if (tid < DD) {
        float s = 0.f;
        #pragma unroll
        for (int t = 0; t < 16; ++t) s += red[t * DD + tid];
        atomicAdd(&g_stats[DD + tid], s);
    }
}

// ---------------------------------------------------------------------------
// Turn column sums into (scale, shift) for the BN affine transform.
// ---------------------------------------------------------------------------
__global__ void finalize_stats(const float* __restrict__ gamma, const float* __restrict__ beta)
{
    int j = threadIdx.x;
    float mu  = g_stats[j] * (1.0f / NN);
    float var = g_stats[DD + j] * (1.0f / NN) - mu * mu;
    float rs  = rsqrtf(var + BN_EPS);
    float s   = gamma[j] * rs;
    g_stats[2 * DD + j] = s;
    g_stats[3 * DD + j] = beta[j] - mu * s;
}

// ---------------------------------------------------------------------------
// In-place BN apply: out = out*scale[col] + shift[col]
// ---------------------------------------------------------------------------
__global__ void bn_apply(float* __restrict__ out)
{
    const int n4 = NN * DD / 4;
    int stride = gridDim.x * blockDim.x;
    float4* o4 = (float4*)out;
    const float4* s4 = (const float4*)(g_stats + 2 * DD);
    const float4* b4 = (const float4*)(g_stats + 3 * DD);
    for (int i = blockIdx.x * blockDim.x + threadIdx.x; i < n4; i += stride) {
        int c = i & 31;
        float4 v = o4[i];
        float4 s = __ldg(s4 + c);
        float4 b = __ldg(b4 + c);
        v.x = fmaf(v.x, s.x, b.x);
        v.y = fmaf(v.y, s.y, b.y);
        v.z = fmaf(v.z, s.z, b.z);
        v.w = fmaf(v.w, s.w, b.w);
        o4[i] = v;
    }
}

// ---------------------------------------------------------------------------
// Inputs (metadata order): x[NN*DD] f32, edge_attr[NE] f32 (UNUSED by reference),
// W_l[DD*DD] f32, b_l[DD] f32, W_r[DD*DD] f32, gamma[DD] f32, beta[DD] f32,
// edge_index[2*NE] i32. Output: [NN*DD] f32.
// ---------------------------------------------------------------------------
extern "C" void kernel_launch(void* const* d_in, const int* in_sizes, int n_in,
                              void* d_out, int out_size)
{
    const float* x     = (const float*)d_in[0];
    const float* Wl    = (const float*)d_in[2];
    const float* bl    = (const float*)d_in[3];
    const float* Wr    = (const float*)d_in[4];
    const float* gamma = (const float*)d_in[5];
    const float* beta  = (const float*)d_in[6];
    const int*   ei    = (const int*)d_in[7];
    float* out = (float*)d_out;

    init_kernel<<<1024, 256>>>();

    scatter_kernel<<<(NE * 32) / 256, 256>>>(x, ei);

    int smem = (KTOT * DD + KTOT * PAD + BM) * (int)sizeof(float);  // ~201 KB
    cudaFuncSetAttribute(fused_gemm, cudaFuncAttributeMaxDynamicSharedMemorySize, smem);
    fused_gemm<<<148, 256, smem>>>(x, Wl, bl, Wr, out);

    finalize_stats<<<1, DD>>>(gamma, beta);
    bn_apply<<<2048, 256>>>(out);
}

// round 4
// speedup vs baseline: 1.4190x; 1.4190x over previous
#include <cuda_runtime.h>
#include <cuda_bf16.h>
#include <cstdint>
#include <cstddef>

// Problem constants
#define NN 100000
#define NE 640000
#define DD 128
#define BN_EPS 1e-5f

#define MT 128                          // rows per tile
#define NTILES ((NN + MT - 1) / MT)     // 782

// Padded smem strides (bf16 elements). Both ≡ 4 banks (mod 32) per row ->
// conflict-free ldmatrix phases (8 rows cover all 32 banks).
#define SA 136      // A chunk: [128 rows][128 k] padded to 136
#define SW 264      // W:       [128 n][256 k]    padded to 264

// smem byte layout
#define SM_BIAS  0
#define SM_INVS  512
#define SM_WHI   1024
#define SM_WLO   (SM_WHI + 128 * SW * 2)          //  1024 + 67584
#define SM_AHI   (SM_WLO + 128 * SW * 2)          // 136192
#define SM_ALO   (SM_AHI + 128 * SA * 2)          // 171008
#define SM_TOTAL (SM_ALO + 128 * SA * 2)          // 205824 B

// Device scratch
__device__ __align__(16) float g_agg[(size_t)NN * DD];
__device__ __align__(16) float g_cnt[NN];
__device__ __align__(16) float g_stats[4 * DD];  // [colsum | colsumsq | scale | shift]

// ---------------- helpers -----------------
__device__ __forceinline__ uint32_t smem_u32(const void* p) {
    uint32_t a;
    asm("{ .reg .u64 t; cvta.to.shared.u64 t, %1; cvt.u32.u64 %0, t; }"
        : "=r"(a) : "l"(p));
    return a;
}

__device__ __forceinline__ void ldsm4(uint32_t* r, uint32_t addr) {
    asm volatile("ldmatrix.sync.aligned.m8n8.x4.shared.b16 {%0,%1,%2,%3}, [%4];"
                 : "=r"(r[0]), "=r"(r[1]), "=r"(r[2]), "=r"(r[3]) : "r"(addr));
}

__device__ __forceinline__ void mma16816(float* d, const uint32_t* a,
                                         uint32_t b0, uint32_t b1) {
    asm volatile(
        "mma.sync.aligned.m16n8k16.row.col.f32.bf16.bf16.f32 "
        "{%0,%1,%2,%3}, {%4,%5,%6,%7}, {%8,%9}, {%0,%1,%2,%3};"
        : "+f"(d[0]), "+f"(d[1]), "+f"(d[2]), "+f"(d[3])
        : "r"(a[0]), "r"(a[1]), "r"(a[2]), "r"(a[3]), "r"(b0), "r"(b1));
}

// Split fp32x4 -> bf16 hi/lo, store 8B each to padded smem row (byte pointers)
__device__ __forceinline__ void store_split(char* hi, char* lo, float4 v) {
    __nv_bfloat16 h0 = __float2bfloat16(v.x);
    __nv_bfloat16 h1 = __float2bfloat16(v.y);
    __nv_bfloat16 h2 = __float2bfloat16(v.z);
    __nv_bfloat16 h3 = __float2bfloat16(v.w);
    __nv_bfloat16 l0 = __float2bfloat16(v.x - __bfloat162float(h0));
    __nv_bfloat16 l1 = __float2bfloat16(v.y - __bfloat162float(h1));
    __nv_bfloat16 l2 = __float2bfloat16(v.z - __bfloat162float(h2));
    __nv_bfloat16 l3 = __float2bfloat16(v.w - __bfloat162float(h3));
    uint32_t hA = (uint32_t)__bfloat16_as_ushort(h0) | ((uint32_t)__bfloat16_as_ushort(h1) << 16);
    uint32_t hB = (uint32_t)__bfloat16_as_ushort(h2) | ((uint32_t)__bfloat16_as_ushort(h3) << 16);
    uint32_t lA = (uint32_t)__bfloat16_as_ushort(l0) | ((uint32_t)__bfloat16_as_ushort(l1) << 16);
    uint32_t lB = (uint32_t)__bfloat16_as_ushort(l2) | ((uint32_t)__bfloat16_as_ushort(l3) << 16);
    *(uint2*)hi = make_uint2(hA, hB);
    *(uint2*)lo = make_uint2(lA, lB);
}

// ---------------------------------------------------------------------------
// init: zero scratch
// ---------------------------------------------------------------------------
__global__ void init_kernel()
{
    const int n4 = NN * DD / 4;
    int stride = gridDim.x * blockDim.x;
    float4 z4 = make_float4(0.f, 0.f, 0.f, 0.f);
    float4* a4 = (float4*)g_agg;
    for (int i = blockIdx.x * blockDim.x + threadIdx.x; i < n4; i += stride)
        a4[i] = z4;
    for (int i = blockIdx.x * blockDim.x + threadIdx.x; i < NN; i += stride)
        g_cnt[i] = 0.f;
    if (blockIdx.x == 0 && threadIdx.x < 2 * DD)
        g_stats[threadIdx.x] = 0.f;
}

// ---------------------------------------------------------------------------
// Scatter: one warp per edge; agg[dst] += relu(x[src]); cnt[dst] += 1
// ---------------------------------------------------------------------------
__global__ void scatter_kernel(const float* __restrict__ x, const int* __restrict__ ei)
{
    int t = blockIdx.x * blockDim.x + threadIdx.x;
    int e = t >> 5;
    if (e >= NE) return;
    int lane = t & 31;
    int src = __ldg(ei + e);
    int dst = __ldg(ei + NE + e);

    float4 v = __ldg((const float4*)(x + (size_t)src * DD) + lane);
    v.x = fmaxf(v.x, 0.f); v.y = fmaxf(v.y, 0.f);
    v.z = fmaxf(v.z, 0.f); v.w = fmaxf(v.w, 0.f);

    float* p = g_agg + (size_t)dst * DD + lane * 4;
    asm volatile("red.global.add.v4.f32 [%0], {%1, %2, %3, %4};"
                 :: "l"(p), "f"(v.x), "f"(v.y), "f"(v.z), "f"(v.w) : "memory");
    if (lane == 0) atomicAdd(&g_cnt[dst], 1.0f);
}

// ---------------------------------------------------------------------------
// Split-bf16 HMMA GEMM + fused BN stats.
//   out[i][j] = sum_k A[i][k]*Wc[j][k] + b_l[j]
//   A = [mean_agg | relu(x)] (K=256), Wc = [W_l | W_r]
//   3 passes per k-step: Ah*Wh + Ah*Wl + Al*Wh  (drops only Al*Wl ~ 2^-16)
// 256 threads = 8 warps: warp (wm=w&3, wn=w>>2) computes rows wm*32..+31,
// cols wn*64..+63 via m16n8k16 mma. Persistent 148 CTAs.
// ---------------------------------------------------------------------------
__global__ void __launch_bounds__(256, 1) mma_gemm(
    const float* __restrict__ x, const float* __restrict__ Wl,
    const float* __restrict__ bl, const float* __restrict__ Wr,
    float* __restrict__ out)
{
    extern __shared__ char smem[];
    const uint32_t sb = smem_u32(smem);
    const int tid  = threadIdx.x;
    const int w    = tid >> 5;
    const int lane = tid & 31;
    const int wm = w & 3, wn = w >> 2;
    const int gid = lane >> 2, tig = lane & 3;

    float* bb   = (float*)(smem + SM_BIAS);
    float* invs = (float*)(smem + SM_INVS);

    if (tid < DD) bb[tid] = __ldg(bl + tid);

    // --- W -> bf16 hi/lo into padded [n][k'] (k' = 0..255), row stride SW ---
    // Per warp: n = i*8 + w (uniform), f4 = lane -> coalesced 512B gmem reads,
    // 8B smem stores.
    #pragma unroll
    for (int i = 0; i < 16; ++i) {
        int n  = i * 8 + w;
        int c0 = lane * 4;
        float4 v = __ldg((const float4*)(Wl + (size_t)n * DD) + lane);
        store_split(smem + SM_WHI + (n * SW + c0) * 2,
                    smem + SM_WLO + (n * SW + c0) * 2, v);
        v = __ldg((const float4*)(Wr + (size_t)n * DD) + lane);
        store_split(smem + SM_WHI + (n * SW + 128 + c0) * 2,
                    smem + SM_WLO + (n * SW + 128 + c0) * 2, v);
    }

    // ldmatrix base addresses (x4 pattern: lanes 0-15 -> 16 rows at k0,
    // lanes 16-31 -> same rows at k0+8)
    const uint32_t aRow = (uint32_t)(wm * 32 + (lane & 15));
    const uint32_t wRow = (uint32_t)(wn * 64 + (lane & 15));
    const uint32_t kOff = (uint32_t)((lane >> 4) * 8);
    const uint32_t aHiB = sb + SM_AHI + (aRow * SA + kOff) * 2;
    const uint32_t aLoB = sb + SM_ALO + (aRow * SA + kOff) * 2;
    const uint32_t wHiB = sb + SM_WHI + (wRow * SW + kOff) * 2;
    const uint32_t wLoB = sb + SM_WLO + (wRow * SW + kOff) * 2;

    float cs[16], cq[16];
    #pragma unroll
    for (int c = 0; c < 16; ++c) { cs[c] = 0.f; cq[c] = 0.f; }

    for (int tile = blockIdx.x; tile < NTILES; tile += gridDim.x) {
        const int rowbase = tile * MT;
        if (tid < MT) {
            int r = rowbase + tid;
            invs[tid] = (r < NN) ? 1.0f / fmaxf(g_cnt[r], 1.0f) : 0.0f;
        }

        float acc[2][8][4];
        #pragma unroll
        for (int mt = 0; mt < 2; ++mt)
            #pragma unroll
            for (int nt = 0; nt < 8; ++nt)
                #pragma unroll
                for (int c = 0; c < 4; ++c) acc[mt][nt][c] = 0.f;

        #pragma unroll
        for (int ch = 0; ch < 2; ++ch) {
            __syncthreads();   // prev reads of A smem done; invs visible
            // --- fill A chunk: row = i*8+w (uniform/warp), f4 = lane ---
            #pragma unroll
            for (int i = 0; i < 16; ++i) {
                int r = i * 8 + w;
                int grow = rowbase + r;
                float4 v = make_float4(0.f, 0.f, 0.f, 0.f);
                if (ch == 0) {
                    if (grow < NN) {
                        v = *((const float4*)(g_agg + (size_t)grow * DD) + lane);
                        float sc = invs[r];
                        v.x *= sc; v.y *= sc; v.z *= sc; v.w *= sc;
                    }
                } else {
                    if (grow < NN) {
                        v = __ldg((const float4*)(x + (size_t)grow * DD) + lane);
                        v.x = fmaxf(v.x, 0.f); v.y = fmaxf(v.y, 0.f);
                        v.z = fmaxf(v.z, 0.f); v.w = fmaxf(v.w, 0.f);
                    }
                }
                int c0 = lane * 4;
                store_split(smem + SM_AHI + (r * SA + c0) * 2,
                            smem + SM_ALO + (r * SA + c0) * 2, v);
            }
            __syncthreads();

            // --- compute: 8 k16-steps, 3 passes each ---
            #pragma unroll
            for (int kt = 0; kt < 8; ++kt) {
                uint32_t ah[2][4], al[2][4], wh[4][4], wlr[4][4];
                const uint32_t ak = (uint32_t)(kt * 32);            // kt*16 cols * 2B
                const uint32_t wk = (uint32_t)((ch * 128 + kt * 16) * 2);
                #pragma unroll
                for (int mt = 0; mt < 2; ++mt) {
                    ldsm4(ah[mt], aHiB + (uint32_t)(mt * 16 * SA * 2) + ak);
                    ldsm4(al[mt], aLoB + (uint32_t)(mt * 16 * SA * 2) + ak);
                }
                #pragma unroll
                for (int np = 0; np < 4; ++np) {
                    ldsm4(wh[np],  wHiB + (uint32_t)(np * 16 * SW * 2) + wk);
                    ldsm4(wlr[np], wLoB + (uint32_t)(np * 16 * SW * 2) + wk);
                }
                // wh[np] = {b0 even-tile, b0 odd-tile, b1 even, b1 odd} for n-tiles 2np,2np+1
                #pragma unroll
                for (int mt = 0; mt < 2; ++mt)
                    #pragma unroll
                    for (int np = 0; np < 4; ++np) {
                        mma16816(acc[mt][2*np],   ah[mt], wh[np][0],  wh[np][2]);
                        mma16816(acc[mt][2*np+1], ah[mt], wh[np][1],  wh[np][3]);
                        mma16816(acc[mt][2*np],   ah[mt], wlr[np][0], wlr[np][2]);
                        mma16816(acc[mt][2*np+1], ah[mt], wlr[np][1], wlr[np][3]);
                        mma16816(acc[mt][2*np],   al[mt], wh[np][0],  wh[np][2]);
                        mma16816(acc[mt][2*np+1], al[mt], wh[np][1],  wh[np][3]);
                    }
            }
        }

        // --- epilogue: bias add, store, BN stats in regs ---
        #pragma unroll
        for (int mt = 0; mt < 2; ++mt) {
            int r0 = rowbase + wm * 32 + mt * 16 + gid;
            int r1 = r0 + 8;
            #pragma unroll
            for (int nt = 0; nt < 8; ++nt) {
                int c0 = wn * 64 + nt * 8 + 2 * tig;
                float b0v = bb[c0], b1v = bb[c0 + 1];
                float v0 = acc[mt][nt][0] + b0v, v1 = acc[mt][nt][1] + b1v;
                float v2 = acc[mt][nt][2] + b0v, v3 = acc[mt][nt][3] + b1v;
                if (r0 < NN) {
                    *(float2*)(out + (size_t)r0 * DD + c0) = make_float2(v0, v1);
                    cs[nt*2]   += v0; cq[nt*2]   += v0 * v0;
                    cs[nt*2+1] += v1; cq[nt*2+1] += v1 * v1;
                }
                if (r1 < NN) {
                    *(float2*)(out + (size_t)r1 * DD + c0) = make_float2(v2, v3);
                    cs[nt*2]   += v2; cq[nt*2]   += v2 * v2;
                    cs[nt*2+1] += v3; cq[nt*2+1] += v3 * v3;
                }
            }
        }
    }

    // --- block reduction of BN stats (A smem reused), then atomics ---
    __syncthreads();
    float* red = (float*)(smem + SM_AHI);   // 256*16 floats = 16KB
    #pragma unroll
    for (int c = 0; c < 16; ++c) red[tid * 16 + c] = cs[c];
    __syncthreads();
    if (tid < DD) {
        int jwn = tid >> 6, nt = (tid >> 3) & 7, jt = (tid >> 1) & 3, p = tid & 1;
        float s = 0.f;
        #pragma unroll
        for (int wm2 = 0; wm2 < 4; ++wm2)
            #pragma unroll
            for (int g2 = 0; g2 < 8; ++g2) {
                int t2 = (jwn * 4 + wm2) * 32 + g2 * 4 + jt;
                s += red[t2 * 16 + nt * 2 + p];
            }
        atomicAdd(&g_stats[tid], s);
    }
    __syncthreads();
    #pragma unroll
    for (int c = 0; c < 16; ++c) red[tid * 16 + c] = cq[c];
    __syncthreads();
    if (tid < DD) {
        int jwn = tid >> 6, nt = (tid >> 3) & 7, jt = (tid >> 1) & 3, p = tid & 1;
        float s = 0.f;
        #pragma unroll
        for (int wm2 = 0; wm2 < 4; ++wm2)
            #pragma unroll
            for (int g2 = 0; g2 < 8; ++g2) {
                int t2 = (jwn * 4 + wm2) * 32 + g2 * 4 + jt;
                s += red[t2 * 16 + nt * 2 + p];
            }
        atomicAdd(&g_stats[DD + tid], s);
    }
}

__global__ void finalize_stats(const float* __restrict__ gamma, const float* __restrict__ beta)
{
    int j = threadIdx.x;
    float mu  = g_stats[j] * (1.0f / NN);
    float var = g_stats[DD + j] * (1.0f / NN) - mu * mu;
    float rs  = rsqrtf(var + BN_EPS);
    float s   = gamma[j] * rs;
    g_stats[2 * DD + j] = s;
    g_stats[3 * DD + j] = beta[j] - mu * s;
}

__global__ void bn_apply(float* __restrict__ out)
{
    const int n4 = NN * DD / 4;
    int stride = gridDim.x * blockDim.x;
    float4* o4 = (float4*)out;
    const float4* s4 = (const float4*)(g_stats + 2 * DD);
    const float4* b4 = (const float4*)(g_stats + 3 * DD);
    for (int i = blockIdx.x * blockDim.x + threadIdx.x; i < n4; i += stride) {
        int c = i & 31;
        float4 v = o4[i];
        float4 s = __ldg(s4 + c);
        float4 b = __ldg(b4 + c);
        v.x = fmaf(v.x, s.x, b.x);
        v.y = fmaf(v.y, s.y, b.y);
        v.z = fmaf(v.z, s.z, b.z);
        v.w = fmaf(v.w, s.w, b.w);
        o4[i] = v;
    }
}

// ---------------------------------------------------------------------------
// Inputs: x, edge_attr(unused), W_l, b_l, W_r, gamma, beta, edge_index
// ---------------------------------------------------------------------------
extern "C" void kernel_launch(void* const* d_in, const int* in_sizes, int n_in,
                              void* d_out, int out_size)
{
    const float* x     = (const float*)d_in[0];
    const float* Wl    = (const float*)d_in[2];
    const float* bl    = (const float*)d_in[3];
    const float* Wr    = (const float*)d_in[4];
    const float* gamma = (const float*)d_in[5];
    const float* beta  = (const float*)d_in[6];
    const int*   ei    = (const int*)d_in[7];
    float* out = (float*)d_out;

    init_kernel<<<1024, 256>>>();
    scatter_kernel<<<(NE * 32) / 256, 256>>>(x, ei);

    cudaFuncSetAttribute(mma_gemm, cudaFuncAttributeMaxDynamicSharedMemorySize, SM_TOTAL);
    mma_gemm<<<148, 256, SM_TOTAL>>>(x, Wl, bl, Wr, out);

    finalize_stats<<<1, DD>>>(gamma, beta);
    bn_apply<<<2048, 256>>>(out);
}

// round 5
// speedup vs baseline: 1.4606x; 1.0293x over previous
#include <cuda_runtime.h>
#include <cuda_bf16.h>
#include <cstdint>
#include <cstddef>

// Problem constants
#define NN 100000
#define NE 640000
#define DD 128
#define BN_EPS 1e-5f

#define MT 128                          // rows per tile
#define NTILES ((NN + MT - 1) / MT)     // 782

// Padded smem strides (bf16 elements); row stride ≡ 4 banks (mod 32) ->
// conflict-free ldmatrix phases.
#define SA 136      // A chunk: [128 rows][128 k]
#define SW 264      // W:       [128 n][256 k]

// smem byte layout
#define SM_BIAS  0
#define SM_WHI   1024
#define SM_WLO   (SM_WHI + 128 * SW * 2)
#define SM_AHI   (SM_WLO + 128 * SW * 2)
#define SM_ALO   (SM_AHI + 128 * SA * 2)
#define SM_TOTAL (SM_ALO + 128 * SA * 2)   // ~205 KB

// Device scratch
__device__ __align__(16) float g_agg[(size_t)NN * DD];
__device__ __align__(16) float g_cnt[NN];
__device__ __align__(16) float g_stats[4 * DD];  // [colsum | colsumsq | scale | shift]

// ---------------- helpers -----------------
__device__ __forceinline__ uint32_t smem_u32(const void* p) {
    uint32_t a;
    asm("{ .reg .u64 t; cvta.to.shared.u64 t, %1; cvt.u32.u64 %0, t; }"
        : "=r"(a) : "l"(p));
    return a;
}

__device__ __forceinline__ void ldsm4(uint32_t* r, uint32_t addr) {
    asm volatile("ldmatrix.sync.aligned.m8n8.x4.shared.b16 {%0,%1,%2,%3}, [%4];"
                 : "=r"(r[0]), "=r"(r[1]), "=r"(r[2]), "=r"(r[3]) : "r"(addr));
}

__device__ __forceinline__ void mma16816(float* d, const uint32_t* a,
                                         uint32_t b0, uint32_t b1) {
    asm volatile(
        "mma.sync.aligned.m16n8k16.row.col.f32.bf16.bf16.f32 "
        "{%0,%1,%2,%3}, {%4,%5,%6,%7}, {%8,%9}, {%0,%1,%2,%3};"
        : "+f"(d[0]), "+f"(d[1]), "+f"(d[2]), "+f"(d[3])
        : "r"(a[0]), "r"(a[1]), "r"(a[2]), "r"(a[3]), "r"(b0), "r"(b1));
}

// Split fp32x4 -> bf16 hi/lo, store 8B each to padded smem row (byte pointers)
__device__ __forceinline__ void store_split(char* hi, char* lo, float4 v) {
    __nv_bfloat16 h0 = __float2bfloat16(v.x);
    __nv_bfloat16 h1 = __float2bfloat16(v.y);
    __nv_bfloat16 h2 = __float2bfloat16(v.z);
    __nv_bfloat16 h3 = __float2bfloat16(v.w);
    __nv_bfloat16 l0 = __float2bfloat16(v.x - __bfloat162float(h0));
    __nv_bfloat16 l1 = __float2bfloat16(v.y - __bfloat162float(h1));
    __nv_bfloat16 l2 = __float2bfloat16(v.z - __bfloat162float(h2));
    __nv_bfloat16 l3 = __float2bfloat16(v.w - __bfloat162float(h3));
    uint32_t hA = (uint32_t)__bfloat16_as_ushort(h0) | ((uint32_t)__bfloat16_as_ushort(h1) << 16);
    uint32_t hB = (uint32_t)__bfloat16_as_ushort(h2) | ((uint32_t)__bfloat16_as_ushort(h3) << 16);
    uint32_t lA = (uint32_t)__bfloat16_as_ushort(l0) | ((uint32_t)__bfloat16_as_ushort(l1) << 16);
    uint32_t lB = (uint32_t)__bfloat16_as_ushort(l2) | ((uint32_t)__bfloat16_as_ushort(l3) << 16);
    *(uint2*)hi = make_uint2(hA, hB);
    *(uint2*)lo = make_uint2(lA, lB);
}

// ---------------------------------------------------------------------------
__global__ void init_kernel()
{
    const int n4 = NN * DD / 4;
    int stride = gridDim.x * blockDim.x;
    float4 z4 = make_float4(0.f, 0.f, 0.f, 0.f);
    float4* a4 = (float4*)g_agg;
    for (int i = blockIdx.x * blockDim.x + threadIdx.x; i < n4; i += stride)
        a4[i] = z4;
    for (int i = blockIdx.x * blockDim.x + threadIdx.x; i < NN; i += stride)
        g_cnt[i] = 0.f;
    if (blockIdx.x == 0 && threadIdx.x < 2 * DD)
        g_stats[threadIdx.x] = 0.f;
}

// ---------------------------------------------------------------------------
__global__ void scatter_kernel(const float* __restrict__ x, const int* __restrict__ ei)
{
    int t = blockIdx.x * blockDim.x + threadIdx.x;
    int e = t >> 5;
    if (e >= NE) return;
    int lane = t & 31;
    int src = __ldg(ei + e);
    int dst = __ldg(ei + NE + e);

    float4 v = __ldg((const float4*)(x + (size_t)src * DD) + lane);
    v.x = fmaxf(v.x, 0.f); v.y = fmaxf(v.y, 0.f);
    v.z = fmaxf(v.z, 0.f); v.w = fmaxf(v.w, 0.f);

    float* p = g_agg + (size_t)dst * DD + lane * 4;
    asm volatile("red.global.add.v4.f32 [%0], {%1, %2, %3, %4};"
                 :: "l"(p), "f"(v.x), "f"(v.y), "f"(v.z), "f"(v.w) : "memory");
    if (lane == 0) atomicAdd(&g_cnt[dst], 1.0f);
}

// ---------------------------------------------------------------------------
// Compute one K=128 chunk: 8 k16-steps x 3 passes, pass-outermost so all 16
// MMAs within a pass hit distinct accumulators (no RAW chains).
// ---------------------------------------------------------------------------
__device__ __forceinline__ void compute_chunk(
    float acc[2][8][4], int ch,
    uint32_t aHiB, uint32_t aLoB, uint32_t wHiB, uint32_t wLoB)
{
    #pragma unroll
    for (int kt = 0; kt < 8; ++kt) {
        uint32_t ah[2][4], al[2][4], wh[4][4], wlr[4][4];
        const uint32_t ak = (uint32_t)(kt * 32);
        const uint32_t wk = (uint32_t)((ch * 128 + kt * 16) * 2);
        #pragma unroll
        for (int mt = 0; mt < 2; ++mt) {
            ldsm4(ah[mt], aHiB + (uint32_t)(mt * 16 * SA * 2) + ak);
            ldsm4(al[mt], aLoB + (uint32_t)(mt * 16 * SA * 2) + ak);
        }
        #pragma unroll
        for (int np = 0; np < 4; ++np) {
            ldsm4(wh[np],  wHiB + (uint32_t)(np * 16 * SW * 2) + wk);
            ldsm4(wlr[np], wLoB + (uint32_t)(np * 16 * SW * 2) + wk);
        }
        // pass 0: Ah*Wh — 16 independent MMAs
        #pragma unroll
        for (int mt = 0; mt < 2; ++mt)
            #pragma unroll
            for (int np = 0; np < 4; ++np) {
                mma16816(acc[mt][2*np],   ah[mt], wh[np][0], wh[np][2]);
                mma16816(acc[mt][2*np+1], ah[mt], wh[np][1], wh[np][3]);
            }
        // pass 1: Ah*Wl
        #pragma unroll
        for (int mt = 0; mt < 2; ++mt)
            #pragma unroll
            for (int np = 0; np < 4; ++np) {
                mma16816(acc[mt][2*np],   ah[mt], wlr[np][0], wlr[np][2]);
                mma16816(acc[mt][2*np+1], ah[mt], wlr[np][1], wlr[np][3]);
            }
        // pass 2: Al*Wh
        #pragma unroll
        for (int mt = 0; mt < 2; ++mt)
            #pragma unroll
            for (int np = 0; np < 4; ++np) {
                mma16816(acc[mt][2*np],   al[mt], wh[np][0], wh[np][2]);
                mma16816(acc[mt][2*np+1], al[mt], wh[np][1], wh[np][3]);
            }
    }
}

// ---------------------------------------------------------------------------
// Split-bf16 HMMA GEMM + fused BN stats, software-pipelined:
//   x LDGs issued before chunk0 compute; next tile's agg LDGs issued before
//   chunk1 compute -> DRAM latency hidden behind MMAs.
// ---------------------------------------------------------------------------
__global__ void __launch_bounds__(256, 1) mma_gemm(
    const float* __restrict__ x, const float* __restrict__ Wl,
    const float* __restrict__ bl, const float* __restrict__ Wr,
    float* __restrict__ out)
{
    extern __shared__ char smem[];
    const uint32_t sb = smem_u32(smem);
    const int tid  = threadIdx.x;
    const int w    = tid >> 5;
    const int lane = tid & 31;
    const int wm = w & 3, wn = w >> 2;
    const int gid = lane >> 2, tig = lane & 3;

    float* bb = (float*)(smem + SM_BIAS);
    if (tid < DD) bb[tid] = __ldg(bl + tid);

    // --- W -> bf16 hi/lo into padded [n][k'], row stride SW ---
    #pragma unroll
    for (int i = 0; i < 16; ++i) {
        int n  = i * 8 + w;
        int c0 = lane * 4;
        float4 v = __ldg((const float4*)(Wl + (size_t)n * DD) + lane);
        store_split(smem + SM_WHI + (n * SW + c0) * 2,
                    smem + SM_WLO + (n * SW + c0) * 2, v);
        v = __ldg((const float4*)(Wr + (size_t)n * DD) + lane);
        store_split(smem + SM_WHI + (n * SW + 128 + c0) * 2,
                    smem + SM_WLO + (n * SW + 128 + c0) * 2, v);
    }

    // ldmatrix base addresses
    const uint32_t aRow = (uint32_t)(wm * 32 + (lane & 15));
    const uint32_t wRow = (uint32_t)(wn * 64 + (lane & 15));
    const uint32_t kOff = (uint32_t)((lane >> 4) * 8);
    const uint32_t aHiB = sb + SM_AHI + (aRow * SA + kOff) * 2;
    const uint32_t aLoB = sb + SM_ALO + (aRow * SA + kOff) * 2;
    const uint32_t wHiB = sb + SM_WHI + (wRow * SW + kOff) * 2;
    const uint32_t wLoB = sb + SM_WLO + (wRow * SW + kOff) * 2;

    float cs[16], cq[16];
    #pragma unroll
    for (int c = 0; c < 16; ++c) { cs[c] = 0.f; cq[c] = 0.f; }

    // --- prefetch tile 0's agg rows + counts ---
    float4 va[16];
    float  c1 = 1.0f;   // lane<16: cnt for row lane*8+w
    {
        const int rowbase = blockIdx.x * MT;
        #pragma unroll
        for (int i = 0; i < 16; ++i) {
            int grow = rowbase + i * 8 + w;
            va[i] = (grow < NN) ? *((const float4*)(g_agg + (size_t)grow * DD) + lane)
                                : make_float4(0.f, 0.f, 0.f, 0.f);
        }
        if (lane < 16) {
            int grow = rowbase + lane * 8 + w;
            c1 = (grow < NN) ? __ldg(g_cnt + grow) : 1.0f;
        }
    }

    for (int tile = blockIdx.x; tile < NTILES; tile += gridDim.x) {
        const int rowbase = tile * MT;

        __syncthreads();   // prev tile's chunk1 ldsm done -> A smem free

        // --- STS chunk0 = mean_agg (scale prefetched rows) ---
        #pragma unroll
        for (int i = 0; i < 16; ++i) {
            float cv = __shfl_sync(0xFFFFFFFFu, c1, i);
            float sc = 1.0f / fmaxf(cv, 1.0f);
            float4 v = va[i];
            v.x *= sc; v.y *= sc; v.z *= sc; v.w *= sc;
            int r = i * 8 + w, c0 = lane * 4;
            store_split(smem + SM_AHI + (r * SA + c0) * 2,
                        smem + SM_ALO + (r * SA + c0) * 2, v);
        }
        __syncthreads();

        // --- issue x LDGs (land during chunk0 compute) ---
        float4 vb[16];
        #pragma unroll
        for (int i = 0; i < 16; ++i) {
            int grow = rowbase + i * 8 + w;
            vb[i] = (grow < NN) ? __ldg((const float4*)(x + (size_t)grow * DD) + lane)
                                : make_float4(0.f, 0.f, 0.f, 0.f);
        }

        float acc[2][8][4];
        #pragma unroll
        for (int mt = 0; mt < 2; ++mt)
            #pragma unroll
            for (int nt = 0; nt < 8; ++nt)
                #pragma unroll
                for (int c = 0; c < 4; ++c) acc[mt][nt][c] = 0.f;

        compute_chunk(acc, 0, aHiB, aLoB, wHiB, wLoB);
        __syncthreads();   // chunk0 ldsm done -> A smem free

        // --- STS chunk1 = relu(x) ---
        #pragma unroll
        for (int i = 0; i < 16; ++i) {
            float4 v = vb[i];
            v.x = fmaxf(v.x, 0.f); v.y = fmaxf(v.y, 0.f);
            v.z = fmaxf(v.z, 0.f); v.w = fmaxf(v.w, 0.f);
            int r = i * 8 + w, c0 = lane * 4;
            store_split(smem + SM_AHI + (r * SA + c0) * 2,
                        smem + SM_ALO + (r * SA + c0) * 2, v);
        }
        __syncthreads();

        // --- prefetch next tile's agg (lands during chunk1 compute) ---
        const int ntile = tile + gridDim.x;
        if (ntile < NTILES) {
            const int nrb = ntile * MT;
            #pragma unroll
            for (int i = 0; i < 16; ++i) {
                int grow = nrb + i * 8 + w;
                va[i] = (grow < NN) ? *((const float4*)(g_agg + (size_t)grow * DD) + lane)
                                    : make_float4(0.f, 0.f, 0.f, 0.f);
            }
            if (lane < 16) {
                int grow = nrb + lane * 8 + w;
                c1 = (grow < NN) ? __ldg(g_cnt + grow) : 1.0f;
            }
        }

        compute_chunk(acc, 1, aHiB, aLoB, wHiB, wLoB);

        // --- epilogue: bias add, store, BN stats in regs ---
        #pragma unroll
        for (int mt = 0; mt < 2; ++mt) {
            int r0 = rowbase + wm * 32 + mt * 16 + gid;
            int r1 = r0 + 8;
            #pragma unroll
            for (int nt = 0; nt < 8; ++nt) {
                int c0 = wn * 64 + nt * 8 + 2 * tig;
                float b0v = bb[c0], b1v = bb[c0 + 1];
                float v0 = acc[mt][nt][0] + b0v, v1 = acc[mt][nt][1] + b1v;
                float v2 = acc[mt][nt][2] + b0v, v3 = acc[mt][nt][3] + b1v;
                if (r0 < NN) {
                    *(float2*)(out + (size_t)r0 * DD + c0) = make_float2(v0, v1);
                    cs[nt*2]   += v0; cq[nt*2]   += v0 * v0;
                    cs[nt*2+1] += v1; cq[nt*2+1] += v1 * v1;
                }
                if (r1 < NN) {
                    *(float2*)(out + (size_t)r1 * DD + c0) = make_float2(v2, v3);
                    cs[nt*2]   += v2; cq[nt*2]   += v2 * v2;
                    cs[nt*2+1] += v3; cq[nt*2+1] += v3 * v3;
                }
            }
        }
    }

    // --- block reduction of BN stats (A smem reused), then atomics ---
    __syncthreads();
    float* red = (float*)(smem + SM_AHI);
    #pragma unroll
    for (int c = 0; c < 16; ++c) red[tid * 16 + c] = cs[c];
    __syncthreads();
    if (tid < DD) {
        int jwn = tid >> 6, nt = (tid >> 3) & 7, jt = (tid >> 1) & 3, p = tid & 1;
        float s = 0.f;
        #pragma unroll
        for (int wm2 = 0; wm2 < 4; ++wm2)
            #pragma unroll
            for (int g2 = 0; g2 < 8; ++g2) {
                int t2 = (jwn * 4 + wm2) * 32 + g2 * 4 + jt;
                s += red[t2 * 16 + nt * 2 + p];
            }
        atomicAdd(&g_stats[tid], s);
    }
    __syncthreads();
    #pragma unroll
    for (int c = 0; c < 16; ++c) red[tid * 16 + c] = cq[c];
    __syncthreads();
    if (tid < DD) {
        int jwn = tid >> 6, nt = (tid >> 3) & 7, jt = (tid >> 1) & 3, p = tid & 1;
        float s = 0.f;
        #pragma unroll
        for (int wm2 = 0; wm2 < 4; ++wm2)
            #pragma unroll
            for (int g2 = 0; g2 < 8; ++g2) {
                int t2 = (jwn * 4 + wm2) * 32 + g2 * 4 + jt;
                s += red[t2 * 16 + nt * 2 + p];
            }
        atomicAdd(&g_stats[DD + tid], s);
    }
}

__global__ void finalize_stats(const float* __restrict__ gamma, const float* __restrict__ beta)
{
    int j = threadIdx.x;
    float mu  = g_stats[j] * (1.0f / NN);
    float var = g_stats[DD + j] * (1.0f / NN) - mu * mu;
    float rs  = rsqrtf(var + BN_EPS);
    float s   = gamma[j] * rs;
    g_stats[2 * DD + j] = s;
    g_stats[3 * DD + j] = beta[j] - mu * s;
}

__global__ void bn_apply(float* __restrict__ out)
{
    const int n4 = NN * DD / 4;
    int stride = gridDim.x * blockDim.x;
    float4* o4 = (float4*)out;
    const float4* s4 = (const float4*)(g_stats + 2 * DD);
    const float4* b4 = (const float4*)(g_stats + 3 * DD);
    for (int i = blockIdx.x * blockDim.x + threadIdx.x; i < n4; i += stride) {
        int c = i & 31;
        float4 v = o4[i];
        float4 s = __ldg(s4 + c);
        float4 b = __ldg(b4 + c);
        v.x = fmaf(v.x, s.x, b.x);
        v.y = fmaf(v.y, s.y, b.y);
        v.z = fmaf(v.z, s.z, b.z);
        v.w = fmaf(v.w, s.w, b.w);
        o4[i] = v;
    }
}

// ---------------------------------------------------------------------------
extern "C" void kernel_launch(void* const* d_in, const int* in_sizes, int n_in,
                              void* d_out, int out_size)
{
    const float* x     = (const float*)d_in[0];
    const float* Wl    = (const float*)d_in[2];
    const float* bl    = (const float*)d_in[3];
    const float* Wr    = (const float*)d_in[4];
    const float* gamma = (const float*)d_in[5];
    const float* beta  = (const float*)d_in[6];
    const int*   ei    = (const int*)d_in[7];
    float* out = (float*)d_out;

    init_kernel<<<1024, 256>>>();
    scatter_kernel<<<(NE * 32) / 256, 256>>>(x, ei);

    cudaFuncSetAttribute(mma_gemm, cudaFuncAttributeMaxDynamicSharedMemorySize, SM_TOTAL);
    mma_gemm<<<148, 256, SM_TOTAL>>>(x, Wl, bl, Wr, out);

    finalize_stats<<<1, DD>>>(gamma, beta);
    bn_apply<<<2048, 256>>>(out);
}